// round 9
// baseline (speedup 1.0000x reference)
#include <cuda_runtime.h>
#include <cstdint>

#define PTS 131072
#define SVOX 131072
#define EPSV 1e-5f
#define MAXP 16

// ---------------- static device scratch ----------------
__device__ float g_Y1[PTS * 64];
__device__ float g_Y2[PTS * 128];
__device__ float g_Y3[PTS * 256];
__device__ float g_Y4[67108864];          // [PTS, 512]
__device__ int   g_cnt[SVOX];
__device__ int   g_slot[SVOX * MAXP];
__device__ float g_part[1024 * 1024];     // per-CTA stats partials
__device__ float g_scale[4][256];
__device__ float g_shift[4][256];
__device__ float g_Wr2[64 * 128];         // tf32-rounded weights [K][N]
__device__ float g_Wr3[128 * 256];
__device__ float g_Wr4[256 * 512];

// ---------------- helpers ----------------
__device__ __forceinline__ uint32_t smem_u32(const void* p) {
    uint32_t a;
    asm("{ .reg .u64 t; cvta.to.shared.u64 t, %1; cvt.u32.u64 %0, t; }" : "=r"(a) : "l"(p));
    return a;
}
__device__ __forceinline__ float to_tf32(float x) {
    uint32_t o; asm("cvt.rna.tf32.f32 %0, %1;" : "=r"(o) : "f"(x));
    return __uint_as_float(o);
}
__device__ __forceinline__ void cp16(uint32_t saddr, const void* g) {
    asm volatile("cp.async.cg.shared.global [%0], [%1], 16;" :: "r"(saddr), "l"(g));
}
#define CP_COMMIT() asm volatile("cp.async.commit_group;" ::: "memory")
#define CP_WAIT0()  asm volatile("cp.async.wait_group 0;" ::: "memory")

__device__ __forceinline__ void mma16n8k8(float* c, const uint32_t* a, const uint32_t* b) {
    asm volatile("mma.sync.aligned.m16n8k8.row.col.f32.tf32.tf32.f32 "
        "{%0,%1,%2,%3}, {%4,%5,%6,%7}, {%8,%9}, {%0,%1,%2,%3};"
        : "+f"(c[0]), "+f"(c[1]), "+f"(c[2]), "+f"(c[3])
        : "r"(a[0]), "r"(a[1]), "r"(a[2]), "r"(a[3]), "r"(b[0]), "r"(b[1]));
}

// ---------------- setup kernels ----------------
// init g_cnt AND round W2/W3/W4 to tf32 (independent work, one launch)
__global__ void init_roundW(const float* __restrict__ W2, const float* __restrict__ W3,
                            const float* __restrict__ W4,
                            float* __restrict__ Wr2, float* __restrict__ Wr3,
                            float* __restrict__ Wr4) {
    int i = blockIdx.x * blockDim.x + threadIdx.x;
    if (i < SVOX) g_cnt[i] = 0;
    const int N2 = 64 * 128, N3 = 128 * 256, N4 = 256 * 512;
    if (i < N2) Wr2[i] = to_tf32(W2[i]);
    int j = i - N2;
    if (j >= 0 && j < N3) Wr3[j] = to_tf32(W3[j]);
    int k = i - N2 - N3;
    if (k >= 0 && k < N4) Wr4[k] = to_tf32(W4[k]);
}

__global__ void keys_kernel(const int* __restrict__ xy) {
    int p = blockIdx.x * blockDim.x + threadIdx.x;
    if (p < PTS) {
        int x = xy[2 * p], y = xy[2 * p + 1];
        int key = ((p >> 16) << 16) | (x << 8) | y;
        int rank = atomicAdd(&g_cnt[key], 1);
        if (rank < MAXP) g_slot[key * MAXP + rank] = p;
    }
}

// ---------------- input stats (C=8 only; later layers fused into GEMMs) ----------------
__global__ void __launch_bounds__(256) stats_part8(const float* __restrict__ Y) {
    const int C = 8, PER = 32;
    int t = threadIdx.x;
    int c = t % C, sl = t / C;
    int r0 = blockIdx.x * (PTS / 256);
    float s = 0.f, q = 0.f;
    for (int r = r0 + sl; r < r0 + PTS / 256; r += PER) {
        float v = Y[(size_t)r * C + c];
        s += v; q += v * v;
    }
    __shared__ float ss[256], sq[256];
    ss[t] = s; sq[t] = q;
    __syncthreads();
    if (sl == 0) {
        for (int i = 1; i < PER; i++) { s += ss[c + i * C]; q += sq[c + i * C]; }
        g_part[(blockIdx.x * 2) * C + c]     = s;
        g_part[(blockIdx.x * 2 + 1) * C + c] = q;
    }
}

template <int C, int NP>
__global__ void __launch_bounds__(256) stats_fin(int L, const float* __restrict__ gam,
                                                 const float* __restrict__ bet) {
    int c = blockIdx.x * 8 + (threadIdx.x >> 5);
    int lane = threadIdx.x & 31;
    if (c >= C) return;
    float s = 0.f, q = 0.f;
    for (int b = lane; b < NP; b += 32) {
        s += g_part[(b * 2) * C + c];
        q += g_part[(b * 2 + 1) * C + c];
    }
#pragma unroll
    for (int o = 16; o; o >>= 1) {
        s += __shfl_down_sync(0xFFFFFFFFu, s, o);
        q += __shfl_down_sync(0xFFFFFFFFu, q, o);
    }
    if (lane == 0) {
        float mean = s / (float)PTS;
        float var  = q / (float)PTS - mean * mean;
        float sc   = gam[c] * rsqrtf(var + EPSV);
        g_scale[L][c] = sc;
        g_shift[L][c] = bet[c] - mean * sc;
    }
}

// ---------------- GEMM1 (K=8, FFMA, exact fp32) + fused Y1 stats ----------------
__global__ void __launch_bounds__(256) gemm1(const float* __restrict__ X, const float* __restrict__ W) {
    __shared__ float Xs[128][9];
    __shared__ float Ws[8][64];
    __shared__ float s1[16][68], q1[16][68];
    int tid = threadIdx.x;
    int m0 = blockIdx.x * 128;
    int row = tid >> 1, c4 = (tid & 1) * 4;
    float4 xv = *(const float4*)(X + (size_t)(m0 + row) * 8 + c4);
    float xa[4] = {xv.x, xv.y, xv.z, xv.w};
#pragma unroll
    for (int j = 0; j < 4; j++)
        Xs[row][c4 + j] = xa[j] * g_scale[0][c4 + j] + g_shift[0][c4 + j];
    if (tid < 128) {
        int r = tid >> 4, cc = (tid & 15) * 4;
        *(float4*)&Ws[r][cc] = *(const float4*)(W + r * 64 + cc);
    }
    __syncthreads();
    int tx = tid & 15, ty = tid >> 4;
    float acc[8][4] = {};
#pragma unroll
    for (int k = 0; k < 8; k++) {
        float4 bv = *(float4*)&Ws[k][tx * 4];
        float b[4] = {bv.x, bv.y, bv.z, bv.w};
#pragma unroll
        for (int i = 0; i < 8; i++) {
            float a = Xs[ty * 8 + i][k];
#pragma unroll
            for (int j = 0; j < 4; j++) acc[i][j] += a * b[j];
        }
    }
#pragma unroll
    for (int i = 0; i < 8; i++) {
        float4 o = make_float4(acc[i][0], acc[i][1], acc[i][2], acc[i][3]);
        *(float4*)&g_Y1[(size_t)(m0 + ty * 8 + i) * 64 + tx * 4] = o;
    }
#pragma unroll
    for (int j = 0; j < 4; j++) {
        float s = 0.f, q = 0.f;
#pragma unroll
        for (int i = 0; i < 8; i++) { float v = acc[i][j]; s += v; q += v * v; }
        s1[ty][tx * 4 + j] = s;
        q1[ty][tx * 4 + j] = q;
    }
    __syncthreads();
    if (tid < 64) {
        float S = 0.f, Q = 0.f;
#pragma unroll
        for (int t = 0; t < 16; t++) { S += s1[t][tid]; Q += q1[t][tid]; }
        g_part[(blockIdx.x * 2) * 64 + tid]     = S;
        g_part[(blockIdx.x * 2 + 1) * 64 + tid] = Q;
    }
}

// ---------------- tf32 mma.sync GEMM ----------------
// Y[M,N] = relu(X*scale[L]+shift[L])[M,K] @ Wr[K,N]
// A staged row-major [m][k] stride-20 -> writer uses 2x STS.128 (was 8 scalar STS),
// reads verified bank-conflict-free (gid*20 mod 32 is a full permutation).
// CTA: 128x128 tile, 8 warps (2x4), warp tile 64x32. BK=16 double-buffered.
template <int K, int NFULL, bool STATS>
__global__ void __launch_bounds__(256) hgemm(const float* __restrict__ X,
                                             const float* __restrict__ Wr,
                                             float* __restrict__ Y, int L) {
    __shared__ __align__(16) float As[2][128][20];   // [m][k], stride 20
    __shared__ __align__(16) float Bs[2][16][136];   // [k][n]
    __shared__ float ssum[2][4][32], ssq[2][4][32];
    const int S = K / 16;

    int tid = threadIdx.x;
    int wid = tid >> 5, lane = tid & 31;
    int warpM = wid & 1, warpN = wid >> 1;
    int gid = lane >> 2, tig = lane & 3;
    int m0 = blockIdx.y * 128;
    int n0 = blockIdx.x * 128;

    const float* scl = g_scale[L];
    const float* shf = g_shift[L];

    const int ar = tid >> 1;            // A row this thread stages
    const int ach = (tid & 1) * 8;      // A k-offset within BK=16
    const int bk = tid >> 4;
    const int bc = (tid & 15) * 8;

    float areg[8];
    auto loadA = [&](int kc) {
        const float4* p = (const float4*)(X + (size_t)(m0 + ar) * K + kc + ach);
        float4 v0 = p[0], v1 = p[1];
        areg[0] = v0.x; areg[1] = v0.y; areg[2] = v0.z; areg[3] = v0.w;
        areg[4] = v1.x; areg[5] = v1.y; areg[6] = v1.z; areg[7] = v1.w;
    };
    auto storeA = [&](int buf, int kc) {
        float v[8];
#pragma unroll
        for (int j = 0; j < 8; j++)
            v[j] = to_tf32(fmaxf(areg[j] * scl[kc + ach + j] + shf[kc + ach + j], 0.f));
        float4* dst = (float4*)&As[buf][ar][ach];
        dst[0] = make_float4(v[0], v[1], v[2], v[3]);
        dst[1] = make_float4(v[4], v[5], v[6], v[7]);
    };
    auto cpB = [&](int buf, int kc) {
        const float* src = Wr + (size_t)(kc + bk) * NFULL + n0 + bc;
        uint32_t dst = smem_u32(&Bs[buf][bk][bc]);
        cp16(dst, src);
        cp16(dst + 16, src + 4);
        CP_COMMIT();
    };

    float acc[4][4][4] = {};

    loadA(0);
    cpB(0, 0);
    storeA(0, 0);
    CP_WAIT0();
    __syncthreads();

    for (int s = 0; s < S; s++) {
        int buf = s & 1;
        if (s + 1 < S) { cpB(buf ^ 1, (s + 1) * 16); loadA((s + 1) * 16); }

#pragma unroll
        for (int kk = 0; kk < 16; kk += 8) {
            uint32_t a[4][4], b[4][2];
#pragma unroll
            for (int mt = 0; mt < 4; mt++) {
                int rb = warpM * 64 + mt * 16 + gid;
                a[mt][0] = __float_as_uint(As[buf][rb][kk + tig]);
                a[mt][1] = __float_as_uint(As[buf][rb + 8][kk + tig]);
                a[mt][2] = __float_as_uint(As[buf][rb][kk + tig + 4]);
                a[mt][3] = __float_as_uint(As[buf][rb + 8][kk + tig + 4]);
            }
#pragma unroll
            for (int nt = 0; nt < 4; nt++) {
                int nb = warpN * 32 + nt * 8 + gid;
                b[nt][0] = __float_as_uint(Bs[buf][kk + tig][nb]);
                b[nt][1] = __float_as_uint(Bs[buf][kk + tig + 4][nb]);
            }
#pragma unroll
            for (int mt = 0; mt < 4; mt++)
#pragma unroll
                for (int nt = 0; nt < 4; nt++)
                    mma16n8k8(acc[mt][nt], a[mt], b[nt]);
        }

        if (s + 1 < S) { storeA(buf ^ 1, (s + 1) * 16); CP_WAIT0(); }
        __syncthreads();
    }

    // ---- Y store ----
#pragma unroll
    for (int mt = 0; mt < 4; mt++) {
#pragma unroll
        for (int half = 0; half < 2; half++) {
            int m = m0 + warpM * 64 + mt * 16 + gid + 8 * half;
            float* yrow = Y + (size_t)m * NFULL + n0;
#pragma unroll
            for (int nt = 0; nt < 4; nt++) {
                int n = warpN * 32 + nt * 8 + 2 * tig;
                float2 o = make_float2(acc[mt][nt][2 * half], acc[mt][nt][2 * half + 1]);
                *(float2*)(yrow + n) = o;
            }
        }
    }

    // ---- fused column stats (raw Y tile), deterministic ----
    if (STATS) {
        float s_[4][2] = {}, q_[4][2] = {};
#pragma unroll
        for (int nt = 0; nt < 4; nt++)
#pragma unroll
            for (int j = 0; j < 2; j++)
#pragma unroll
                for (int mt = 0; mt < 4; mt++)
#pragma unroll
                    for (int half = 0; half < 2; half++) {
                        float v = acc[mt][nt][2 * half + j];
                        s_[nt][j] += v; q_[nt][j] += v * v;
                    }
#pragma unroll
        for (int o = 16; o >= 4; o >>= 1)
#pragma unroll
            for (int nt = 0; nt < 4; nt++)
#pragma unroll
                for (int j = 0; j < 2; j++) {
                    s_[nt][j] += __shfl_down_sync(0xFFFFFFFFu, s_[nt][j], o);
                    q_[nt][j] += __shfl_down_sync(0xFFFFFFFFu, q_[nt][j], o);
                }
        if (lane < 4) {
#pragma unroll
            for (int nt = 0; nt < 4; nt++)
#pragma unroll
                for (int j = 0; j < 2; j++) {
                    ssum[warpM][warpN][nt * 8 + 2 * lane + j] = s_[nt][j];
                    ssq[warpM][warpN][nt * 8 + 2 * lane + j]  = q_[nt][j];
                }
        }
        __syncthreads();
        if (tid < 128) {
            int wN = tid >> 5, cl = tid & 31;
            float S2 = ssum[0][wN][cl] + ssum[1][wN][cl];
            float Q2 = ssq[0][wN][cl] + ssq[1][wN][cl];
            int col = n0 + wN * 32 + cl;
            g_part[(blockIdx.y * 2) * NFULL + col]     = S2;
            g_part[(blockIdx.y * 2 + 1) * NFULL + col] = Q2;
        }
    }
}

// ---------------- output: gather-max over voxel slots + relu(@Wc), transposed ----------------
__global__ void __launch_bounds__(256) outker(const float* __restrict__ Wc, float* __restrict__ out) {
    __shared__ float sm[32][129];
    __shared__ int scnt[32];
    __shared__ int sslot[32][MAXP];
    int tid = threadIdx.x;
    int vbase = blockIdx.x * 32;
    int vi = tid & 31, cg = tid >> 5;
    if (tid < 32) scnt[tid] = min(g_cnt[vbase + tid], MAXP);
    __syncthreads();
#pragma unroll
    for (int e = 0; e < 2; e++) {
        int idx = tid + 256 * e;
        int v = idx >> 4, s = idx & (MAXP - 1);
        if (s < scnt[v]) sslot[v][s] = g_slot[(vbase + v) * MAXP + s];
    }
    __syncthreads();

    float acc[4] = {0.f, 0.f, 0.f, 0.f};
    for (int kc = 0; kc < 512; kc += 128) {
#pragma unroll
        for (int i = 0; i < 4; i++) {
            int q = tid + 256 * i;
            int row = q >> 5, col = (q & 31) * 4;
            int cn = scnt[row];
            float4 mx = make_float4(0.f, 0.f, 0.f, 0.f);
            if (cn > 0) {
                mx = *(const float4*)(g_Y4 + (size_t)sslot[row][0] * 512 + kc + col);
                for (int j = 1; j < cn; j++) {
                    float4 t = *(const float4*)(g_Y4 + (size_t)sslot[row][j] * 512 + kc + col);
                    mx.x = fmaxf(mx.x, t.x); mx.y = fmaxf(mx.y, t.y);
                    mx.z = fmaxf(mx.z, t.z); mx.w = fmaxf(mx.w, t.w);
                }
            }
            sm[row][col + 0] = mx.x; sm[row][col + 1] = mx.y;
            sm[row][col + 2] = mx.z; sm[row][col + 3] = mx.w;
        }
        __syncthreads();
#pragma unroll 4
        for (int k = 0; k < 128; k++) {
            float p = sm[vi][k];
            float4 w = *(const float4*)(Wc + (size_t)(kc + k) * 32 + cg * 4);
            acc[0] += p * w.x; acc[1] += p * w.y; acc[2] += p * w.z; acc[3] += p * w.w;
        }
        __syncthreads();
    }

    int v = vbase + vi;
    bool oc = scnt[vi] > 0;
    int b = v >> 16, hw = v & 65535;
#pragma unroll
    for (int j = 0; j < 4; j++) {
        float r = oc ? fmaxf(acc[j], 0.f) : 0.f;
        out[(size_t)(b * 32 + cg * 4 + j) * 65536 + hw] = r;
    }
}

// ---------------- launcher ----------------
extern "C" void kernel_launch(void* const* d_in, const int* in_sizes, int n_in,
                              void* d_out, int out_size) {
    (void)in_sizes; (void)n_in; (void)out_size;
    const float* pt_fea = (const float*)d_in[0];
    const float* bn0_g  = (const float*)d_in[1];
    const float* bn0_b  = (const float*)d_in[2];
    const float* W1     = (const float*)d_in[3];
    const float* bn1_g  = (const float*)d_in[4];
    const float* bn1_b  = (const float*)d_in[5];
    const float* W2     = (const float*)d_in[6];
    const float* bn2_g  = (const float*)d_in[7];
    const float* bn2_b  = (const float*)d_in[8];
    const float* W3     = (const float*)d_in[9];
    const float* bn3_g  = (const float*)d_in[10];
    const float* bn3_b  = (const float*)d_in[11];
    const float* W4     = (const float*)d_in[12];
    const float* Wc     = (const float*)d_in[13];
    const int*   xy     = (const int*)d_in[14];
    float* out = (float*)d_out;

    float *Y1p, *Y2p, *Y3p, *Y4p, *Wr2p, *Wr3p, *Wr4p;
    cudaGetSymbolAddress((void**)&Y1p, g_Y1);
    cudaGetSymbolAddress((void**)&Y2p, g_Y2);
    cudaGetSymbolAddress((void**)&Y3p, g_Y3);
    cudaGetSymbolAddress((void**)&Y4p, g_Y4);
    cudaGetSymbolAddress((void**)&Wr2p, g_Wr2);
    cudaGetSymbolAddress((void**)&Wr3p, g_Wr3);
    cudaGetSymbolAddress((void**)&Wr4p, g_Wr4);

    const int NW = 64 * 128 + 128 * 256 + 256 * 512;   // 172032 > SVOX
    init_roundW<<<(NW + 255) / 256, 256>>>(W2, W3, W4, Wr2p, Wr3p, Wr4p);
    keys_kernel<<<512, 256>>>(xy);

    stats_part8<<<256, 256>>>(pt_fea);
    stats_fin<8, 256><<<1, 256>>>(0, bn0_g, bn0_b);

    gemm1<<<1024, 256>>>(pt_fea, W1);
    stats_fin<64, 1024><<<8, 256>>>(1, bn1_g, bn1_b);

    hgemm<64, 128, true><<<dim3(1, 1024), 256>>>(Y1p, Wr2p, Y2p, 1);
    stats_fin<128, 1024><<<16, 256>>>(2, bn2_g, bn2_b);

    hgemm<128, 256, true><<<dim3(2, 1024), 256>>>(Y2p, Wr3p, Y3p, 2);
    stats_fin<256, 1024><<<32, 256>>>(3, bn3_g, bn3_b);

    hgemm<256, 512, false><<<dim3(4, 1024), 256>>>(Y3p, Wr4p, Y4p, 3);

    outker<<<4096, 256>>>(Wc, out);
}

// round 12
// speedup vs baseline: 1.0008x; 1.0008x over previous
#include <cuda_runtime.h>
#include <cstdint>

#define PTS 131072
#define SVOX 131072
#define EPSV 1e-5f
#define MAXP 16

// ---------------- static device scratch ----------------
__device__ float g_Y1[PTS * 64];
__device__ float g_Y2[PTS * 128];
__device__ float g_Y3[PTS * 256];
__device__ float g_Y4[67108864];          // [PTS, 512]
__device__ int   g_cnt[SVOX];             // zero at module load; outker re-zeroes after use
__device__ int   g_slot[SVOX * MAXP];
__device__ float g_part[1024 * 1024];     // per-CTA stats partials
__device__ float g_scale[4][256];
__device__ float g_shift[4][256];
__device__ float g_Wr2[64 * 128];         // tf32-rounded weights [K][N]
__device__ float g_Wr3[128 * 256];
__device__ float g_Wr4[256 * 512];

// ---------------- helpers ----------------
__device__ __forceinline__ uint32_t smem_u32(const void* p) {
    uint32_t a;
    asm("{ .reg .u64 t; cvta.to.shared.u64 t, %1; cvt.u32.u64 %0, t; }" : "=r"(a) : "l"(p));
    return a;
}
__device__ __forceinline__ float to_tf32(float x) {
    uint32_t o; asm("cvt.rna.tf32.f32 %0, %1;" : "=r"(o) : "f"(x));
    return __uint_as_float(o);
}
__device__ __forceinline__ void cp16(uint32_t saddr, const void* g) {
    asm volatile("cp.async.cg.shared.global [%0], [%1], 16;" :: "r"(saddr), "l"(g));
}
#define CP_COMMIT() asm volatile("cp.async.commit_group;" ::: "memory")
#define CP_WAIT0()  asm volatile("cp.async.wait_group 0;" ::: "memory")

__device__ __forceinline__ void mma16n8k8(float* c, const uint32_t* a, const uint32_t* b) {
    asm volatile("mma.sync.aligned.m16n8k8.row.col.f32.tf32.tf32.f32 "
        "{%0,%1,%2,%3}, {%4,%5,%6,%7}, {%8,%9}, {%0,%1,%2,%3};"
        : "+f"(c[0]), "+f"(c[1]), "+f"(c[2]), "+f"(c[3])
        : "r"(a[0]), "r"(a[1]), "r"(a[2]), "r"(a[3]), "r"(b[0]), "r"(b[1]));
}

// ---------------- setup: tf32-rounded weights (launch 0) ----------------
__global__ void roundW_all(const float* __restrict__ W2, const float* __restrict__ W3,
                           const float* __restrict__ W4,
                           float* __restrict__ Wr2, float* __restrict__ Wr3,
                           float* __restrict__ Wr4) {
    int i = blockIdx.x * blockDim.x + threadIdx.x;
    const int N2 = 64 * 128, N3 = 128 * 256, N4 = 256 * 512;
    if (i < N2) Wr2[i] = to_tf32(W2[i]);
    int j = i - N2;
    if (j >= 0 && j < N3) Wr3[j] = to_tf32(W3[j]);
    int k = i - N2 - N3;
    if (k >= 0 && k < N4) Wr4[k] = to_tf32(W4[k]);
}

// keys: g_cnt is guaranteed zero here (module-load init or previous outker cleanup)
__global__ void keys_kernel(const int* __restrict__ xy) {
    int p = blockIdx.x * blockDim.x + threadIdx.x;
    if (p < PTS) {
        int x = xy[2 * p], y = xy[2 * p + 1];
        int key = ((p >> 16) << 16) | (x << 8) | y;
        int rank = atomicAdd(&g_cnt[key], 1);
        if (rank < MAXP) g_slot[key * MAXP + rank] = p;
    }
}

// ---------------- input stats (C=8 only; later layers fused into GEMMs) ----------------
__global__ void __launch_bounds__(256) stats_part8(const float* __restrict__ Y) {
    const int C = 8, PER = 32;
    int t = threadIdx.x;
    int c = t % C, sl = t / C;
    int r0 = blockIdx.x * (PTS / 256);
    float s = 0.f, q = 0.f;
    for (int r = r0 + sl; r < r0 + PTS / 256; r += PER) {
        float v = Y[(size_t)r * C + c];
        s += v; q += v * v;
    }
    __shared__ float ss[256], sq[256];
    ss[t] = s; sq[t] = q;
    __syncthreads();
    if (sl == 0) {
        for (int i = 1; i < PER; i++) { s += ss[c + i * C]; q += sq[c + i * C]; }
        g_part[(blockIdx.x * 2) * C + c]     = s;
        g_part[(blockIdx.x * 2 + 1) * C + c] = q;
    }
}

template <int C, int NP>
__global__ void __launch_bounds__(256) stats_fin(int L, const float* __restrict__ gam,
                                                 const float* __restrict__ bet) {
    int c = blockIdx.x * 8 + (threadIdx.x >> 5);
    int lane = threadIdx.x & 31;
    if (c >= C) return;
    float s = 0.f, q = 0.f;
    for (int b = lane; b < NP; b += 32) {
        s += g_part[(b * 2) * C + c];
        q += g_part[(b * 2 + 1) * C + c];
    }
#pragma unroll
    for (int o = 16; o; o >>= 1) {
        s += __shfl_down_sync(0xFFFFFFFFu, s, o);
        q += __shfl_down_sync(0xFFFFFFFFu, q, o);
    }
    if (lane == 0) {
        float mean = s / (float)PTS;
        float var  = q / (float)PTS - mean * mean;
        float sc   = gam[c] * rsqrtf(var + EPSV);
        g_scale[L][c] = sc;
        g_shift[L][c] = bet[c] - mean * sc;
    }
}

// ---------------- GEMM1 (K=8, FFMA, exact fp32) + fused Y1 stats ----------------
__global__ void __launch_bounds__(256) gemm1(const float* __restrict__ X, const float* __restrict__ W) {
    __shared__ float Xs[128][9];
    __shared__ float Ws[8][64];
    __shared__ float s1[16][68], q1[16][68];
    int tid = threadIdx.x;
    int m0 = blockIdx.x * 128;
    int row = tid >> 1, c4 = (tid & 1) * 4;
    float4 xv = *(const float4*)(X + (size_t)(m0 + row) * 8 + c4);
    float xa[4] = {xv.x, xv.y, xv.z, xv.w};
#pragma unroll
    for (int j = 0; j < 4; j++)
        Xs[row][c4 + j] = xa[j] * g_scale[0][c4 + j] + g_shift[0][c4 + j];
    if (tid < 128) {
        int r = tid >> 4, cc = (tid & 15) * 4;
        *(float4*)&Ws[r][cc] = *(const float4*)(W + r * 64 + cc);
    }
    __syncthreads();
    int tx = tid & 15, ty = tid >> 4;
    float acc[8][4] = {};
#pragma unroll
    for (int k = 0; k < 8; k++) {
        float4 bv = *(float4*)&Ws[k][tx * 4];
        float b[4] = {bv.x, bv.y, bv.z, bv.w};
#pragma unroll
        for (int i = 0; i < 8; i++) {
            float a = Xs[ty * 8 + i][k];
#pragma unroll
            for (int j = 0; j < 4; j++) acc[i][j] += a * b[j];
        }
    }
#pragma unroll
    for (int i = 0; i < 8; i++) {
        float4 o = make_float4(acc[i][0], acc[i][1], acc[i][2], acc[i][3]);
        *(float4*)&g_Y1[(size_t)(m0 + ty * 8 + i) * 64 + tx * 4] = o;
    }
#pragma unroll
    for (int j = 0; j < 4; j++) {
        float s = 0.f, q = 0.f;
#pragma unroll
        for (int i = 0; i < 8; i++) { float v = acc[i][j]; s += v; q += v * v; }
        s1[ty][tx * 4 + j] = s;
        q1[ty][tx * 4 + j] = q;
    }
    __syncthreads();
    if (tid < 64) {
        float S = 0.f, Q = 0.f;
#pragma unroll
        for (int t = 0; t < 16; t++) { S += s1[t][tid]; Q += q1[t][tid]; }
        g_part[(blockIdx.x * 2) * 64 + tid]     = S;
        g_part[(blockIdx.x * 2 + 1) * 64 + tid] = Q;
    }
}

// ---------------- tf32 mma.sync GEMM (fused column stats) ----------------
// Y[M,N] = relu(X*scale[L]+shift[L])[M,K] @ Wr[K,N]
// A staged row-major [m][k] stride-20; grid = (N/128, M/128).
// CTA: 128x128 tile, 8 warps (2x4), warp tile 64x32. BK=16 double-buffered.
template <int K, int NFULL, bool STATS>
__global__ void __launch_bounds__(256) hgemm(const float* __restrict__ X,
                                             const float* __restrict__ Wr,
                                             float* __restrict__ Y, int L) {
    __shared__ __align__(16) float As[2][128][20];
    __shared__ __align__(16) float Bs[2][16][136];
    __shared__ float ssum[2][4][32], ssq[2][4][32];
    const int S = K / 16;

    int tid = threadIdx.x;
    int wid = tid >> 5, lane = tid & 31;
    int warpM = wid & 1, warpN = wid >> 1;
    int gid = lane >> 2, tig = lane & 3;
    int m0 = blockIdx.y * 128;
    int n0 = blockIdx.x * 128;

    const float* scl = g_scale[L];
    const float* shf = g_shift[L];

    const int ar = tid >> 1;
    const int ach = (tid & 1) * 8;
    const int bk = tid >> 4;
    const int bc = (tid & 15) * 8;

    float areg[8];
    auto loadA = [&](int kc) {
        const float4* p = (const float4*)(X + (size_t)(m0 + ar) * K + kc + ach);
        float4 v0 = p[0], v1 = p[1];
        areg[0] = v0.x; areg[1] = v0.y; areg[2] = v0.z; areg[3] = v0.w;
        areg[4] = v1.x; areg[5] = v1.y; areg[6] = v1.z; areg[7] = v1.w;
    };
    auto storeA = [&](int buf, int kc) {
        float v[8];
#pragma unroll
        for (int j = 0; j < 8; j++)
            v[j] = to_tf32(fmaxf(areg[j] * scl[kc + ach + j] + shf[kc + ach + j], 0.f));
        float4* dst = (float4*)&As[buf][ar][ach];
        dst[0] = make_float4(v[0], v[1], v[2], v[3]);
        dst[1] = make_float4(v[4], v[5], v[6], v[7]);
    };
    auto cpB = [&](int buf, int kc) {
        const float* src = Wr + (size_t)(kc + bk) * NFULL + n0 + bc;
        uint32_t dst = smem_u32(&Bs[buf][bk][bc]);
        cp16(dst, src);
        cp16(dst + 16, src + 4);
        CP_COMMIT();
    };

    float acc[4][4][4] = {};

    loadA(0);
    cpB(0, 0);
    storeA(0, 0);
    CP_WAIT0();
    __syncthreads();

    for (int s = 0; s < S; s++) {
        int buf = s & 1;
        if (s + 1 < S) { cpB(buf ^ 1, (s + 1) * 16); loadA((s + 1) * 16); }

#pragma unroll
        for (int kk = 0; kk < 16; kk += 8) {
            uint32_t a[4][4], b[4][2];
#pragma unroll
            for (int mt = 0; mt < 4; mt++) {
                int rb = warpM * 64 + mt * 16 + gid;
                a[mt][0] = __float_as_uint(As[buf][rb][kk + tig]);
                a[mt][1] = __float_as_uint(As[buf][rb + 8][kk + tig]);
                a[mt][2] = __float_as_uint(As[buf][rb][kk + tig + 4]);
                a[mt][3] = __float_as_uint(As[buf][rb + 8][kk + tig + 4]);
            }
#pragma unroll
            for (int nt = 0; nt < 4; nt++) {
                int nb = warpN * 32 + nt * 8 + gid;
                b[nt][0] = __float_as_uint(Bs[buf][kk + tig][nb]);
                b[nt][1] = __float_as_uint(Bs[buf][kk + tig + 4][nb]);
            }
#pragma unroll
            for (int mt = 0; mt < 4; mt++)
#pragma unroll
                for (int nt = 0; nt < 4; nt++)
                    mma16n8k8(acc[mt][nt], a[mt], b[nt]);
        }

        if (s + 1 < S) { storeA(buf ^ 1, (s + 1) * 16); CP_WAIT0(); }
        __syncthreads();
    }

    // ---- Y store ----
#pragma unroll
    for (int mt = 0; mt < 4; mt++) {
#pragma unroll
        for (int half = 0; half < 2; half++) {
            int m = m0 + warpM * 64 + mt * 16 + gid + 8 * half;
            float* yrow = Y + (size_t)m * NFULL + n0;
#pragma unroll
            for (int nt = 0; nt < 4; nt++) {
                int n = warpN * 32 + nt * 8 + 2 * tig;
                float2 o = make_float2(acc[mt][nt][2 * half], acc[mt][nt][2 * half + 1]);
                *(float2*)(yrow + n) = o;
            }
        }
    }

    // ---- fused column stats (raw Y tile), deterministic ----
    if (STATS) {
        float s_[4][2] = {}, q_[4][2] = {};
#pragma unroll
        for (int nt = 0; nt < 4; nt++)
#pragma unroll
            for (int j = 0; j < 2; j++)
#pragma unroll
                for (int mt = 0; mt < 4; mt++)
#pragma unroll
                    for (int half = 0; half < 2; half++) {
                        float v = acc[mt][nt][2 * half + j];
                        s_[nt][j] += v; q_[nt][j] += v * v;
                    }
#pragma unroll
        for (int o = 16; o >= 4; o >>= 1)
#pragma unroll
            for (int nt = 0; nt < 4; nt++)
#pragma unroll
                for (int j = 0; j < 2; j++) {
                    s_[nt][j] += __shfl_down_sync(0xFFFFFFFFu, s_[nt][j], o);
                    q_[nt][j] += __shfl_down_sync(0xFFFFFFFFu, q_[nt][j], o);
                }
        if (lane < 4) {
#pragma unroll
            for (int nt = 0; nt < 4; nt++)
#pragma unroll
                for (int j = 0; j < 2; j++) {
                    ssum[warpM][warpN][nt * 8 + 2 * lane + j] = s_[nt][j];
                    ssq[warpM][warpN][nt * 8 + 2 * lane + j]  = q_[nt][j];
                }
        }
        __syncthreads();
        if (tid < 128) {
            int wN = tid >> 5, cl = tid & 31;
            float S2 = ssum[0][wN][cl] + ssum[1][wN][cl];
            float Q2 = ssq[0][wN][cl] + ssq[1][wN][cl];
            int col = n0 + wN * 32 + cl;
            g_part[(blockIdx.y * 2) * NFULL + col]     = S2;
            g_part[(blockIdx.y * 2 + 1) * NFULL + col] = Q2;
        }
    }
}

// ---------------- output: gather-max over voxel slots + relu(@Wc), transposed ----------------
// Also self-cleans g_cnt for the next kernel_launch invocation (deterministic).
__global__ void __launch_bounds__(256) outker(const float* __restrict__ Wc, float* __restrict__ out) {
    __shared__ float sm[32][129];
    __shared__ int scnt[32];
    __shared__ int sslot[32][MAXP];
    int tid = threadIdx.x;
    int vbase = blockIdx.x * 32;
    int vi = tid & 31, cg = tid >> 5;
    if (tid < 32) scnt[tid] = min(g_cnt[vbase + tid], MAXP);
    __syncthreads();
#pragma unroll
    for (int e = 0; e < 2; e++) {
        int idx = tid + 256 * e;
        int v = idx >> 4, s = idx & (MAXP - 1);
        if (s < scnt[v]) sslot[v][s] = g_slot[(vbase + v) * MAXP + s];
    }
    __syncthreads();
    if (tid < 32) g_cnt[vbase + tid] = 0;   // self-clean for next launch

    float acc[4] = {0.f, 0.f, 0.f, 0.f};
    for (int kc = 0; kc < 512; kc += 128) {
#pragma unroll
        for (int i = 0; i < 4; i++) {
            int q = tid + 256 * i;
            int row = q >> 5, col = (q & 31) * 4;
            int cn = scnt[row];
            float4 mx = make_float4(0.f, 0.f, 0.f, 0.f);
            if (cn > 0) {
                mx = *(const float4*)(g_Y4 + (size_t)sslot[row][0] * 512 + kc + col);
                for (int j = 1; j < cn; j++) {
                    float4 t = *(const float4*)(g_Y4 + (size_t)sslot[row][j] * 512 + kc + col);
                    mx.x = fmaxf(mx.x, t.x); mx.y = fmaxf(mx.y, t.y);
                    mx.z = fmaxf(mx.z, t.z); mx.w = fmaxf(mx.w, t.w);
                }
            }
            sm[row][col + 0] = mx.x; sm[row][col + 1] = mx.y;
            sm[row][col + 2] = mx.z; sm[row][col + 3] = mx.w;
        }
        __syncthreads();
#pragma unroll 4
        for (int k = 0; k < 128; k++) {
            float p = sm[vi][k];
            float4 w = *(const float4*)(Wc + (size_t)(kc + k) * 32 + cg * 4);
            acc[0] += p * w.x; acc[1] += p * w.y; acc[2] += p * w.z; acc[3] += p * w.w;
        }
        __syncthreads();
    }

    int v = vbase + vi;
    bool oc = scnt[vi] > 0;
    int b = v >> 16, hw = v & 65535;
#pragma unroll
    for (int j = 0; j < 4; j++) {
        float r = oc ? fmaxf(acc[j], 0.f) : 0.f;
        out[(size_t)(b * 32 + cg * 4 + j) * 65536 + hw] = r;
    }
}

// ---------------- launcher ----------------
extern "C" void kernel_launch(void* const* d_in, const int* in_sizes, int n_in,
                              void* d_out, int out_size) {
    (void)in_sizes; (void)n_in; (void)out_size;
    const float* pt_fea = (const float*)d_in[0];
    const float* bn0_g  = (const float*)d_in[1];
    const float* bn0_b  = (const float*)d_in[2];
    const float* W1     = (const float*)d_in[3];
    const float* bn1_g  = (const float*)d_in[4];
    const float* bn1_b  = (const float*)d_in[5];
    const float* W2     = (const float*)d_in[6];
    const float* bn2_g  = (const float*)d_in[7];
    const float* bn2_b  = (const float*)d_in[8];
    const float* W3     = (const float*)d_in[9];
    const float* bn3_g  = (const float*)d_in[10];
    const float* bn3_b  = (const float*)d_in[11];
    const float* W4     = (const float*)d_in[12];
    const float* Wc     = (const float*)d_in[13];
    const int*   xy     = (const int*)d_in[14];
    float* out = (float*)d_out;

    float *Y1p, *Y2p, *Y3p, *Y4p, *Wr2p, *Wr3p, *Wr4p;
    cudaGetSymbolAddress((void**)&Y1p, g_Y1);
    cudaGetSymbolAddress((void**)&Y2p, g_Y2);
    cudaGetSymbolAddress((void**)&Y3p, g_Y3);
    cudaGetSymbolAddress((void**)&Y4p, g_Y4);
    cudaGetSymbolAddress((void**)&Wr2p, g_Wr2);
    cudaGetSymbolAddress((void**)&Wr3p, g_Wr3);
    cudaGetSymbolAddress((void**)&Wr4p, g_Wr4);

    const int NW = 64 * 128 + 128 * 256 + 256 * 512;
    roundW_all<<<(NW + 255) / 256, 256>>>(W2, W3, W4, Wr2p, Wr3p, Wr4p);   // 0

    stats_part8<<<256, 256>>>(pt_fea);                                      // 1
    stats_fin<8, 256><<<1, 256>>>(0, bn0_g, bn0_b);                         // 2

    gemm1<<<1024, 256>>>(pt_fea, W1);                                       // 3
    stats_fin<64, 1024><<<8, 256>>>(1, bn1_g, bn1_b);                       // 4

    hgemm<64, 128, true><<<dim3(1, 1024), 256>>>(Y1p, Wr2p, Y2p, 1);        // 5 <- ncu
    stats_fin<128, 1024><<<16, 256>>>(2, bn2_g, bn2_b);                     // 6

    hgemm<128, 256, true><<<dim3(2, 1024), 256>>>(Y2p, Wr3p, Y3p, 2);       // 7
    stats_fin<256, 1024><<<32, 256>>>(3, bn3_g, bn3_b);                     // 8

    hgemm<256, 512, false><<<dim3(4, 1024), 256>>>(Y3p, Wr4p, Y4p, 3);      // 9

    keys_kernel<<<512, 256>>>(xy);                                          // 10
    outker<<<4096, 256>>>(Wc, out);                                         // 11
}

// round 15
// speedup vs baseline: 1.1596x; 1.1587x over previous
#include <cuda_runtime.h>
#include <cuda_fp16.h>
#include <cstdint>

#define PTS 131072
#define SVOX 131072
#define EPSV 1e-5f
#define MAXP 16

// ---------------- static device scratch ----------------
__device__ float g_Y1[PTS * 64];
__device__ float g_Y2[PTS * 128];
__device__ float g_Y3[PTS * 256];
__device__ float g_Y4[67108864];          // [PTS, 512]
__device__ int   g_cnt[SVOX];             // zero at module load; outker re-zeroes after use
__device__ int   g_slot[SVOX * MAXP];
__device__ float g_part[1024 * 1024];     // per-CTA stats partials
__device__ float g_scale[4][256];
__device__ float g_shift[4][256];
__device__ __half g_WT2[128 * 64];        // W^T as fp16: [N][K]
__device__ __half g_WT3[256 * 128];
__device__ __half g_WT4[512 * 256];

// ---------------- helpers ----------------
__device__ __forceinline__ uint32_t smem_u32(const void* p) {
    uint32_t a;
    asm("{ .reg .u64 t; cvta.to.shared.u64 t, %1; cvt.u32.u64 %0, t; }" : "=r"(a) : "l"(p));
    return a;
}
__device__ __forceinline__ void cp16(uint32_t saddr, const void* g) {
    asm volatile("cp.async.cg.shared.global [%0], [%1], 16;" :: "r"(saddr), "l"(g));
}
#define CP_COMMIT() asm volatile("cp.async.commit_group;" ::: "memory")
#define CP_WAIT0()  asm volatile("cp.async.wait_group 0;" ::: "memory")

// m16n8k16 fp16 MMA, fp32 accumulate
__device__ __forceinline__ void mma_f16(float* c, const uint32_t* a, const uint32_t* b) {
    asm volatile("mma.sync.aligned.m16n8k16.row.col.f32.f16.f16.f32 "
        "{%0,%1,%2,%3}, {%4,%5,%6,%7}, {%8,%9}, {%0,%1,%2,%3};"
        : "+f"(c[0]), "+f"(c[1]), "+f"(c[2]), "+f"(c[3])
        : "r"(a[0]), "r"(a[1]), "r"(a[2]), "r"(a[3]), "r"(b[0]), "r"(b[1]));
}

// ---------------- setup: fp16 transposed weights (launch 0) ----------------
__global__ void prepWT(const float* __restrict__ W2, const float* __restrict__ W3,
                       const float* __restrict__ W4) {
    int i = blockIdx.x * blockDim.x + threadIdx.x;
    if (i < 128 * 64)  { int n = i / 64,  k = i % 64;  g_WT2[i] = __float2half(W2[k * 128 + n]); }
    if (i < 256 * 128) { int n = i / 128, k = i % 128; g_WT3[i] = __float2half(W3[k * 256 + n]); }
    if (i < 512 * 256) { int n = i / 256, k = i % 256; g_WT4[i] = __float2half(W4[k * 512 + n]); }
}

// keys: g_cnt is guaranteed zero here (module-load init or previous outker cleanup)
__global__ void keys_kernel(const int* __restrict__ xy) {
    int p = blockIdx.x * blockDim.x + threadIdx.x;
    if (p < PTS) {
        int x = xy[2 * p], y = xy[2 * p + 1];
        int key = ((p >> 16) << 16) | (x << 8) | y;
        int rank = atomicAdd(&g_cnt[key], 1);
        if (rank < MAXP) g_slot[key * MAXP + rank] = p;
    }
}

// ---------------- input stats (C=8 only; later layers fused into GEMMs) ----------------
__global__ void __launch_bounds__(256) stats_part8(const float* __restrict__ Y) {
    const int C = 8, PER = 32;
    int t = threadIdx.x;
    int c = t % C, sl = t / C;
    int r0 = blockIdx.x * (PTS / 256);
    float s = 0.f, q = 0.f;
    for (int r = r0 + sl; r < r0 + PTS / 256; r += PER) {
        float v = Y[(size_t)r * C + c];
        s += v; q += v * v;
    }
    __shared__ float ss[256], sq[256];
    ss[t] = s; sq[t] = q;
    __syncthreads();
    if (sl == 0) {
        for (int i = 1; i < PER; i++) { s += ss[c + i * C]; q += sq[c + i * C]; }
        g_part[(blockIdx.x * 2) * C + c]     = s;
        g_part[(blockIdx.x * 2 + 1) * C + c] = q;
    }
}

template <int C, int NP>
__global__ void __launch_bounds__(256) stats_fin(int L, const float* __restrict__ gam,
                                                 const float* __restrict__ bet) {
    int c = blockIdx.x * 8 + (threadIdx.x >> 5);
    int lane = threadIdx.x & 31;
    if (c >= C) return;
    float s = 0.f, q = 0.f;
    for (int b = lane; b < NP; b += 32) {
        s += g_part[(b * 2) * C + c];
        q += g_part[(b * 2 + 1) * C + c];
    }
#pragma unroll
    for (int o = 16; o; o >>= 1) {
        s += __shfl_down_sync(0xFFFFFFFFu, s, o);
        q += __shfl_down_sync(0xFFFFFFFFu, q, o);
    }
    if (lane == 0) {
        float mean = s / (float)PTS;
        float var  = q / (float)PTS - mean * mean;
        float sc   = gam[c] * rsqrtf(var + EPSV);
        g_scale[L][c] = sc;
        g_shift[L][c] = bet[c] - mean * sc;
    }
}

// ---------------- GEMM1 (K=8, FFMA, exact fp32) + fused Y1 stats ----------------
__global__ void __launch_bounds__(256) gemm1(const float* __restrict__ X, const float* __restrict__ W) {
    __shared__ float Xs[128][9];
    __shared__ float Ws[8][64];
    __shared__ float s1[16][68], q1[16][68];
    int tid = threadIdx.x;
    int m0 = blockIdx.x * 128;
    int row = tid >> 1, c4 = (tid & 1) * 4;
    float4 xv = *(const float4*)(X + (size_t)(m0 + row) * 8 + c4);
    float xa[4] = {xv.x, xv.y, xv.z, xv.w};
#pragma unroll
    for (int j = 0; j < 4; j++)
        Xs[row][c4 + j] = xa[j] * g_scale[0][c4 + j] + g_shift[0][c4 + j];
    if (tid < 128) {
        int r = tid >> 4, cc = (tid & 15) * 4;
        *(float4*)&Ws[r][cc] = *(const float4*)(W + r * 64 + cc);
    }
    __syncthreads();
    int tx = tid & 15, ty = tid >> 4;
    float acc[8][4] = {};
#pragma unroll
    for (int k = 0; k < 8; k++) {
        float4 bv = *(float4*)&Ws[k][tx * 4];
        float b[4] = {bv.x, bv.y, bv.z, bv.w};
#pragma unroll
        for (int i = 0; i < 8; i++) {
            float a = Xs[ty * 8 + i][k];
#pragma unroll
            for (int j = 0; j < 4; j++) acc[i][j] += a * b[j];
        }
    }
#pragma unroll
    for (int i = 0; i < 8; i++) {
        float4 o = make_float4(acc[i][0], acc[i][1], acc[i][2], acc[i][3]);
        *(float4*)&g_Y1[(size_t)(m0 + ty * 8 + i) * 64 + tx * 4] = o;
    }
#pragma unroll
    for (int j = 0; j < 4; j++) {
        float s = 0.f, q = 0.f;
#pragma unroll
        for (int i = 0; i < 8; i++) { float v = acc[i][j]; s += v; q += v * v; }
        s1[ty][tx * 4 + j] = s;
        q1[ty][tx * 4 + j] = q;
    }
    __syncthreads();
    if (tid < 64) {
        float S = 0.f, Q = 0.f;
#pragma unroll
        for (int t = 0; t < 16; t++) { S += s1[t][tid]; Q += q1[t][tid]; }
        g_part[(blockIdx.x * 2) * 64 + tid]     = S;
        g_part[(blockIdx.x * 2 + 1) * 64 + tid] = Q;
    }
}

// ---------------- fp16 mma.sync GEMM (m16n8k16), fused column stats ----------------
// Y[M,N] = relu(X*scale[L]+shift[L])[M,K] @ W[K,N], A/B in fp16, accumulate fp32.
// A smem: half [m][24] (stride 48B: 8-row bank pattern tiles all 32 banks once).
// B smem: half [n][24] from WT[N][K] (col operand -> [n][k] rows give contiguous half2 frags).
// CTA: 128x128 tile, 8 warps (2x4), warp tile 64x32. BK=16 double-buffered.
template <int K, int NFULL, bool STATS>
__global__ void __launch_bounds__(256) hgemm(const float* __restrict__ X,
                                             const __half* __restrict__ WT,
                                             float* __restrict__ Y, int L) {
    __shared__ __align__(16) __half As[2][128][24];
    __shared__ __align__(16) __half Bs[2][128][24];
    __shared__ float ssum[2][4][32], ssq[2][4][32];
    const int S = K / 16;

    int tid = threadIdx.x;
    int wid = tid >> 5, lane = tid & 31;
    int warpM = wid & 1, warpN = wid >> 1;
    int gid = lane >> 2, tig = lane & 3;
    int m0 = blockIdx.y * 128;
    int n0 = blockIdx.x * 128;

    const float* scl = g_scale[L];
    const float* shf = g_shift[L];

    const int ar = tid >> 1;            // A row this thread stages
    const int ach = (tid & 1) * 8;      // A k-offset within BK=16
    const int br = tid >> 1;            // B row (n) this thread copies
    const int bch = (tid & 1) * 8;      // B k-offset

    float areg[8];
    auto loadA = [&](int kc) {
        const float4* p = (const float4*)(X + (size_t)(m0 + ar) * K + kc + ach);
        float4 v0 = p[0], v1 = p[1];
        areg[0] = v0.x; areg[1] = v0.y; areg[2] = v0.z; areg[3] = v0.w;
        areg[4] = v1.x; areg[5] = v1.y; areg[6] = v1.z; areg[7] = v1.w;
    };
    auto storeA = [&](int buf, int kc) {
        uint32_t h[4];
#pragma unroll
        for (int j = 0; j < 4; j++) {
            float lo = fmaxf(areg[2 * j]     * scl[kc + ach + 2 * j]     + shf[kc + ach + 2 * j], 0.f);
            float hi = fmaxf(areg[2 * j + 1] * scl[kc + ach + 2 * j + 1] + shf[kc + ach + 2 * j + 1], 0.f);
            __half2 p2 = __floats2half2_rn(lo, hi);
            h[j] = *(uint32_t*)&p2;
        }
        uint32_t addr = smem_u32(&As[buf][ar][ach]);
        asm volatile("st.shared.v4.b32 [%0], {%1,%2,%3,%4};"
            :: "r"(addr), "r"(h[0]), "r"(h[1]), "r"(h[2]), "r"(h[3]) : "memory");
    };
    auto cpB = [&](int buf, int kc) {
        const __half* src = WT + (size_t)(n0 + br) * K + kc + bch;
        cp16(smem_u32(&Bs[buf][br][bch]), src);
        CP_COMMIT();
    };

    float acc[4][4][4] = {};

    loadA(0);
    cpB(0, 0);
    storeA(0, 0);
    CP_WAIT0();
    __syncthreads();

    for (int s = 0; s < S; s++) {
        int buf = s & 1;
        if (s + 1 < S) { cpB(buf ^ 1, (s + 1) * 16); loadA((s + 1) * 16); }

        // one k16 step covers the whole BK=16 stage
        {
            uint32_t a[4][4], b[4][2];
#pragma unroll
            for (int mt = 0; mt < 4; mt++) {
                int rb = warpM * 64 + mt * 16 + gid;
                a[mt][0] = *(uint32_t*)&As[buf][rb][2 * tig];
                a[mt][1] = *(uint32_t*)&As[buf][rb + 8][2 * tig];
                a[mt][2] = *(uint32_t*)&As[buf][rb][2 * tig + 8];
                a[mt][3] = *(uint32_t*)&As[buf][rb + 8][2 * tig + 8];
            }
#pragma unroll
            for (int nt = 0; nt < 4; nt++) {
                int nb = warpN * 32 + nt * 8 + gid;
                b[nt][0] = *(uint32_t*)&Bs[buf][nb][2 * tig];
                b[nt][1] = *(uint32_t*)&Bs[buf][nb][2 * tig + 8];
            }
#pragma unroll
            for (int mt = 0; mt < 4; mt++)
#pragma unroll
                for (int nt = 0; nt < 4; nt++)
                    mma_f16(acc[mt][nt], a[mt], b[nt]);
        }

        if (s + 1 < S) { storeA(buf ^ 1, (s + 1) * 16); CP_WAIT0(); }
        __syncthreads();
    }

    // ---- Y store ----
#pragma unroll
    for (int mt = 0; mt < 4; mt++) {
#pragma unroll
        for (int half = 0; half < 2; half++) {
            int m = m0 + warpM * 64 + mt * 16 + gid + 8 * half;
            float* yrow = Y + (size_t)m * NFULL + n0;
#pragma unroll
            for (int nt = 0; nt < 4; nt++) {
                int n = warpN * 32 + nt * 8 + 2 * tig;
                float2 o = make_float2(acc[mt][nt][2 * half], acc[mt][nt][2 * half + 1]);
                *(float2*)(yrow + n) = o;
            }
        }
    }

    // ---- fused column stats (raw Y tile), deterministic ----
    if (STATS) {
        float s_[4][2] = {}, q_[4][2] = {};
#pragma unroll
        for (int nt = 0; nt < 4; nt++)
#pragma unroll
            for (int j = 0; j < 2; j++)
#pragma unroll
                for (int mt = 0; mt < 4; mt++)
#pragma unroll
                    for (int half = 0; half < 2; half++) {
                        float v = acc[mt][nt][2 * half + j];
                        s_[nt][j] += v; q_[nt][j] += v * v;
                    }
#pragma unroll
        for (int o = 16; o >= 4; o >>= 1)
#pragma unroll
            for (int nt = 0; nt < 4; nt++)
#pragma unroll
                for (int j = 0; j < 2; j++) {
                    s_[nt][j] += __shfl_down_sync(0xFFFFFFFFu, s_[nt][j], o);
                    q_[nt][j] += __shfl_down_sync(0xFFFFFFFFu, q_[nt][j], o);
                }
        if (lane < 4) {
#pragma unroll
            for (int nt = 0; nt < 4; nt++)
#pragma unroll
                for (int j = 0; j < 2; j++) {
                    ssum[warpM][warpN][nt * 8 + 2 * lane + j] = s_[nt][j];
                    ssq[warpM][warpN][nt * 8 + 2 * lane + j]  = q_[nt][j];
                }
        }
        __syncthreads();
        if (tid < 128) {
            int wN = tid >> 5, cl = tid & 31;
            float S2 = ssum[0][wN][cl] + ssum[1][wN][cl];
            float Q2 = ssq[0][wN][cl] + ssq[1][wN][cl];
            int col = n0 + wN * 32 + cl;
            g_part[(blockIdx.y * 2) * NFULL + col]     = S2;
            g_part[(blockIdx.y * 2 + 1) * NFULL + col] = Q2;
        }
    }
}

// ---------------- output: gather-max over voxel slots + relu(@Wc), transposed ----------------
// Also self-cleans g_cnt for the next kernel_launch invocation (deterministic).
__global__ void __launch_bounds__(256) outker(const float* __restrict__ Wc, float* __restrict__ out) {
    __shared__ float sm[32][129];
    __shared__ int scnt[32];
    __shared__ int sslot[32][MAXP];
    int tid = threadIdx.x;
    int vbase = blockIdx.x * 32;
    int vi = tid & 31, cg = tid >> 5;
    if (tid < 32) scnt[tid] = min(g_cnt[vbase + tid], MAXP);
    __syncthreads();
#pragma unroll
    for (int e = 0; e < 2; e++) {
        int idx = tid + 256 * e;
        int v = idx >> 4, s = idx & (MAXP - 1);
        if (s < scnt[v]) sslot[v][s] = g_slot[(vbase + v) * MAXP + s];
    }
    __syncthreads();
    if (tid < 32) g_cnt[vbase + tid] = 0;   // self-clean for next launch

    float acc[4] = {0.f, 0.f, 0.f, 0.f};
    for (int kc = 0; kc < 512; kc += 128) {
#pragma unroll
        for (int i = 0; i < 4; i++) {
            int q = tid + 256 * i;
            int row = q >> 5, col = (q & 31) * 4;
            int cn = scnt[row];
            float4 mx = make_float4(0.f, 0.f, 0.f, 0.f);
            if (cn > 0) {
                mx = *(const float4*)(g_Y4 + (size_t)sslot[row][0] * 512 + kc + col);
                for (int j = 1; j < cn; j++) {
                    float4 t = *(const float4*)(g_Y4 + (size_t)sslot[row][j] * 512 + kc + col);
                    mx.x = fmaxf(mx.x, t.x); mx.y = fmaxf(mx.y, t.y);
                    mx.z = fmaxf(mx.z, t.z); mx.w = fmaxf(mx.w, t.w);
                }
            }
            sm[row][col + 0] = mx.x; sm[row][col + 1] = mx.y;
            sm[row][col + 2] = mx.z; sm[row][col + 3] = mx.w;
        }
        __syncthreads();
#pragma unroll 4
        for (int k = 0; k < 128; k++) {
            float p = sm[vi][k];
            float4 w = *(const float4*)(Wc + (size_t)(kc + k) * 32 + cg * 4);
            acc[0] += p * w.x; acc[1] += p * w.y; acc[2] += p * w.z; acc[3] += p * w.w;
        }
        __syncthreads();
    }

    int v = vbase + vi;
    bool oc = scnt[vi] > 0;
    int b = v >> 16, hw = v & 65535;
#pragma unroll
    for (int j = 0; j < 4; j++) {
        float r = oc ? fmaxf(acc[j], 0.f) : 0.f;
        out[(size_t)(b * 32 + cg * 4 + j) * 65536 + hw] = r;
    }
}

// ---------------- launcher ----------------
extern "C" void kernel_launch(void* const* d_in, const int* in_sizes, int n_in,
                              void* d_out, int out_size) {
    (void)in_sizes; (void)n_in; (void)out_size;
    const float* pt_fea = (const float*)d_in[0];
    const float* bn0_g  = (const float*)d_in[1];
    const float* bn0_b  = (const float*)d_in[2];
    const float* W1     = (const float*)d_in[3];
    const float* bn1_g  = (const float*)d_in[4];
    const float* bn1_b  = (const float*)d_in[5];
    const float* W2     = (const float*)d_in[6];
    const float* bn2_g  = (const float*)d_in[7];
    const float* bn2_b  = (const float*)d_in[8];
    const float* W3     = (const float*)d_in[9];
    const float* bn3_g  = (const float*)d_in[10];
    const float* bn3_b  = (const float*)d_in[11];
    const float* W4     = (const float*)d_in[12];
    const float* Wc     = (const float*)d_in[13];
    const int*   xy     = (const int*)d_in[14];
    float* out = (float*)d_out;

    float *Y1p, *Y2p, *Y3p, *Y4p;
    __half *WT2p, *WT3p, *WT4p;
    cudaGetSymbolAddress((void**)&Y1p, g_Y1);
    cudaGetSymbolAddress((void**)&Y2p, g_Y2);
    cudaGetSymbolAddress((void**)&Y3p, g_Y3);
    cudaGetSymbolAddress((void**)&Y4p, g_Y4);
    cudaGetSymbolAddress((void**)&WT2p, g_WT2);
    cudaGetSymbolAddress((void**)&WT3p, g_WT3);
    cudaGetSymbolAddress((void**)&WT4p, g_WT4);

    prepWT<<<512, 256>>>(W2, W3, W4);                                       // 0

    stats_part8<<<256, 256>>>(pt_fea);                                      // 1
    stats_fin<8, 256><<<1, 256>>>(0, bn0_g, bn0_b);                         // 2

    gemm1<<<1024, 256>>>(pt_fea, W1);                                       // 3
    stats_fin<64, 1024><<<8, 256>>>(1, bn1_g, bn1_b);                       // 4

    hgemm<64, 128, true><<<dim3(1, 1024), 256>>>(Y1p, WT2p, Y2p, 1);        // 5
    stats_fin<128, 1024><<<16, 256>>>(2, bn2_g, bn2_b);                     // 6

    hgemm<128, 256, true><<<dim3(2, 1024), 256>>>(Y2p, WT3p, Y3p, 2);       // 7
    stats_fin<256, 1024><<<32, 256>>>(3, bn3_g, bn3_b);                     // 8

    hgemm<256, 512, false><<<dim3(4, 1024), 256>>>(Y3p, WT4p, Y4p, 3);      // 9

    keys_kernel<<<512, 256>>>(xy);                                          // 10
    outker<<<4096, 256>>>(Wc, out);                                         // 11
}